// round 8
// baseline (speedup 1.0000x reference)
#include <cuda_runtime.h>

// QLSTM closed form:
//   qgate(x, p)[:, w] = prod_{j<=w} cos(p[j,1]) * cos(y[:,j] + p[j,0])
// LSTM cell + residual + layernorm; sequential over T only, independent per row.

#define TT 128
#define BB 256
#define DD 64
#define HH 10
#define G4 40   // 4 gates * H
#define WROW (DD + HH)   // 74: row stride of Wg

// Layout: pre[b][t][ch]  (row-contiguous so each scan warp streams 20KB)
__device__ float g_pre[BB * TT * G4];

__device__ __forceinline__ float tanh_fast(float x) {
    float y;
    asm("tanh.approx.f32 %0, %1;" : "=f"(y) : "f"(x));
    return y;
}
__device__ __forceinline__ float sig_fast(float x) {
    return fmaf(0.5f, tanh_fast(0.5f * x), 0.5f);
}

// ---------------------------------------------------------------------------
// Kernel 1 (proven): pre[b][t][:] = fold_bias + x[t,b,:] @ Wg^T
// fold_bias = b_g[w] + p_g[w,0] + sum_j lnb_j * Whh_g[w,j]
// ---------------------------------------------------------------------------
__global__ void __launch_bounds__(128) k_pre(
    const float* __restrict__ x,
    const float* __restrict__ Wf, const float* __restrict__ bf, const float* __restrict__ pf,
    const float* __restrict__ Wi, const float* __restrict__ bi, const float* __restrict__ pi,
    const float* __restrict__ Wu, const float* __restrict__ bu, const float* __restrict__ pu,
    const float* __restrict__ Wo, const float* __restrict__ bo, const float* __restrict__ po,
    const float* __restrict__ lnb_)
{
    int tid  = threadIdx.x;
    int warp = tid >> 5, l = tid & 31;
    int wg   = blockIdx.x * 4 + warp;     // 0..4095
    int b    = wg & (BB - 1);
    int tg   = wg >> 8;                    // 0..15
    int tbase = tg * 8;

    int g0 = l / 10, w0 = l - g0 * 10;
    const float* Wg0 = (g0 == 0) ? Wf : (g0 == 1) ? Wi : (g0 == 2) ? Wu : Wo;
    const float* bg0 = (g0 == 0) ? bf : (g0 == 1) ? bi : (g0 == 2) ? bu : bo;
    const float* pg0 = (g0 == 0) ? pf : (g0 == 1) ? pi : (g0 == 2) ? pu : po;

    float wa[DD];
    #pragma unroll
    for (int d = 0; d < DD; d++) wa[d] = Wg0[w0 * WROW + d];
    float bias0 = bg0[w0] + pg0[w0 * 3 + 0];
    #pragma unroll
    for (int j = 0; j < HH; j++)
        bias0 = fmaf(lnb_[j], Wg0[w0 * WROW + DD + j], bias0);

    float wb[DD];
    float bias1 = 0.f;
    int w1 = 2 + l;
    #pragma unroll
    for (int d = 0; d < DD; d++) wb[d] = (l < 8) ? Wo[w1 * WROW + d] : 0.f;
    if (l < 8) {
        bias1 = bo[w1] + po[w1 * 3 + 0];
        #pragma unroll
        for (int j = 0; j < HH; j++)
            bias1 = fmaf(lnb_[j], Wo[w1 * WROW + DD + j], bias1);
    }

    for (int i = 0; i < 8; i++) {
        int t = tbase + i;
        const float* xr = x + ((size_t)t * BB + b) * DD;
        float x0 = xr[l];
        float x1 = xr[l + 32];

        float a0 = bias0, a0b = 0.f;
        float a1 = bias1, a1b = 0.f;
        #pragma unroll
        for (int d = 0; d < 32; d += 2) {
            float xd0 = __shfl_sync(0xffffffffu, x0, d);
            float xd1 = __shfl_sync(0xffffffffu, x0, d + 1);
            a0  = fmaf(xd0, wa[d], a0);
            a0b = fmaf(xd1, wa[d + 1], a0b);
            a1  = fmaf(xd0, wb[d], a1);
            a1b = fmaf(xd1, wb[d + 1], a1b);
        }
        #pragma unroll
        for (int d = 0; d < 32; d += 2) {
            float xd0 = __shfl_sync(0xffffffffu, x1, d);
            float xd1 = __shfl_sync(0xffffffffu, x1, d + 1);
            a0  = fmaf(xd0, wa[32 + d], a0);
            a0b = fmaf(xd1, wa[32 + d + 1], a0b);
            a1  = fmaf(xd0, wb[32 + d], a1);
            a1b = fmaf(xd1, wb[32 + d + 1], a1b);
        }
        float* pr = g_pre + ((size_t)b * TT + t) * G4;
        pr[l] = a0 + a0b;
        if (l < 8) pr[32 + l] = a1 + a1b;
    }
}

// ---------------------------------------------------------------------------
// Kernel 2: identical per-warp code to the proven R7 version, but launched
// 16 blocks x 512 threads -> 16 warps/SM, 4 warps/SMSP. The 4 co-resident
// independent row-chains hide each other's latency in hardware (the R6
// software interleave done right).
// ---------------------------------------------------------------------------
#define WPB 16   // warps per block
__global__ void __launch_bounds__(WPB * 32) k_scan(
    const float* __restrict__ Wf, const float* __restrict__ pf,
    const float* __restrict__ Wi, const float* __restrict__ pi,
    const float* __restrict__ Wu, const float* __restrict__ pu,
    const float* __restrict__ Wo, const float* __restrict__ po,
    const float* __restrict__ lng_, const float* __restrict__ lnb_,
    float* __restrict__ out)
{
    __shared__ __align__(16) float qs[WPB][2][48];

    int tid  = threadIdx.x;
    int warp = tid >> 5, l = tid & 31;
    int row  = blockIdx.x * WPB + warp;

    int g0 = l / 10, w0 = l - g0 * 10;
    const float* Wg0 = (g0 == 0) ? Wf : (g0 == 1) ? Wi : (g0 == 2) ? Wu : Wo;
    const float* Pg0 = (g0 == 0) ? pf : (g0 == 1) ? pi : (g0 == 2) ? pu : po;

    float cth1_0 = cosf(Pg0[w0 * 3 + 1]);
    float whh0[HH];
    #pragma unroll
    for (int j = 0; j < HH; j++)
        whh0[j] = Wg0[w0 * WROW + DD + j] * lng_[j];

    int w1 = 2 + l;
    float cth1_1 = 0.f;
    float whh1[HH];
    #pragma unroll
    for (int j = 0; j < HH; j++) whh1[j] = 0.f;
    if (l < 8) {
        cth1_1 = cosf(po[w1 * 3 + 1]);
        #pragma unroll
        for (int j = 0; j < HH; j++)
            whh1[j] = Wo[w1 * WROW + DD + j] * lng_[j];
    }

    float lng_l = 0.f, lnb_l = 0.f;
    if (l < HH) { lng_l = lng_[l]; lnb_l = lnb_[l]; }

    float dm[HH];
    #pragma unroll
    for (int j = 0; j < HH; j++) dm[j] = 0.f;
    float rs = 0.f, hown = 0.f, creg = 0.f;

    const float* prow = g_pre + (size_t)row * TT * G4;
    float preA0 = prow[l];
    float preA1 = (l < 8) ? prow[32 + l] : 0.f;
    float preB0 = prow[G4 + l];
    float preB1 = (l < 8) ? prow[G4 + 32 + l] : 0.f;

    float* outp = out + (size_t)row * HH;
    const size_t ostride = (size_t)BB * HH;

#define STEP_BODY(PF0, PF1)                                                     \
    {                                                                           \
        float a0 = 0.f, a1 = 0.f, a2 = 0.f, a3 = 0.f;                           \
        float c0 = 0.f, c1 = 0.f, c2 = 0.f, c3 = 0.f;                           \
        a0 = fmaf(dm[0], whh0[0], a0);  c0 = fmaf(dm[0], whh1[0], c0);          \
        a1 = fmaf(dm[1], whh0[1], a1);  c1 = fmaf(dm[1], whh1[1], c1);          \
        a2 = fmaf(dm[2], whh0[2], a2);  c2 = fmaf(dm[2], whh1[2], c2);          \
        a3 = fmaf(dm[3], whh0[3], a3);  c3 = fmaf(dm[3], whh1[3], c3);          \
        a0 = fmaf(dm[4], whh0[4], a0);  c0 = fmaf(dm[4], whh1[4], c0);          \
        a1 = fmaf(dm[5], whh0[5], a1);  c1 = fmaf(dm[5], whh1[5], c1);          \
        a2 = fmaf(dm[6], whh0[6], a2);  c2 = fmaf(dm[6], whh1[6], c2);          \
        a3 = fmaf(dm[7], whh0[7], a3);  c3 = fmaf(dm[7], whh1[7], c3);          \
        a0 = fmaf(dm[8], whh0[8], a0);  c0 = fmaf(dm[8], whh1[8], c0);          \
        a1 = fmaf(dm[9], whh0[9], a1);  c1 = fmaf(dm[9], whh1[9], c1);          \
        float y0 = fmaf(rs, (a0 + a1) + (a2 + a3), preA0);                      \
        float y1 = fmaf(rs, (c0 + c1) + (c2 + c3), preA1);                      \
        float q0 = cth1_0 * __cosf(y0);                                         \
        float q1 = cth1_1 * __cosf(y1);                                         \
        int par = t & 1;                                                        \
        qs[warp][par][g0 * 12 + w0] = q0;                                       \
        if (l < 8) qs[warp][par][3 * 12 + w1] = q1;                             \
        __syncwarp();                                                           \
        float q[4][10];                                                         \
        _Pragma("unroll")                                                       \
        for (int g = 0; g < 4; g++) {                                           \
            float4 va = *(const float4*)&qs[warp][par][g * 12 + 0];             \
            float4 vb = *(const float4*)&qs[warp][par][g * 12 + 4];             \
            float2 vc = *(const float2*)&qs[warp][par][g * 12 + 8];             \
            q[g][0] = va.x; q[g][1] = va.y; q[g][2] = va.z; q[g][3] = va.w;     \
            q[g][4] = vb.x; q[g][5] = vb.y; q[g][6] = vb.z; q[g][7] = vb.w;     \
            q[g][8] = vc.x; q[g][9] = vc.y;                                     \
        }                                                                       \
        float qm[4][10];                                                        \
        _Pragma("unroll")                                                       \
        for (int g = 0; g < 4; g++) {                                           \
            qm[g][0] = q[g][0];                                                 \
            _Pragma("unroll")                                                   \
            for (int j = 1; j < HH; j++)                                        \
                qm[g][j] = (l >= j) ? q[g][j] : 1.f;                            \
        }                                                                       \
        float p[4];                                                             \
        _Pragma("unroll")                                                       \
        for (int g = 0; g < 4; g++) {                                           \
            float m01 = qm[g][0] * qm[g][1];                                    \
            float m23 = qm[g][2] * qm[g][3];                                    \
            float m45 = qm[g][4] * qm[g][5];                                    \
            float m67 = qm[g][6] * qm[g][7];                                    \
            float m89 = qm[g][8] * qm[g][9];                                    \
            p[g] = ((m01 * m23) * (m45 * m67)) * m89;                           \
        }                                                                       \
        float fg = sig_fast(p[0]);                                              \
        float ig = sig_fast(p[1]);                                              \
        float gg = tanh_fast(p[2]);                                             \
        float og = sig_fast(p[3]);                                              \
        creg = fmaf(fg, creg, ig * gg);                                         \
        float hval = fmaf(og, tanh_fast(creg), hown);                           \
        float hr[HH];                                                           \
        _Pragma("unroll")                                                       \
        for (int j = 0; j < HH; j++) hr[j] = __shfl_sync(0xffffffffu, hval, j); \
        float s0 = (hr[0] + hr[1]) + (hr[2] + hr[3]);                           \
        float s1 = (hr[4] + hr[5]) + (hr[6] + hr[7]);                           \
        float mu = (s0 + s1 + (hr[8] + hr[9])) * 0.1f;                          \
        _Pragma("unroll")                                                       \
        for (int j = 0; j < HH; j++) dm[j] = hr[j] - mu;                        \
        float v0 = 0.f, v1 = 0.f;                                               \
        _Pragma("unroll")                                                       \
        for (int j = 0; j < HH; j += 2) {                                       \
            v0 = fmaf(dm[j],     dm[j],     v0);                                \
            v1 = fmaf(dm[j + 1], dm[j + 1], v1);                                \
        }                                                                       \
        rs   = rsqrtf((v0 + v1) * 0.1f + 1e-5f);                                \
        hown = fmaf((hval - mu) * rs, lng_l, lnb_l);                            \
        if (l < HH) outp[l] = hown;                                             \
        outp += ostride;                                                        \
        preA0 = preB0; preA1 = preB1;                                           \
        preB0 = (PF0); preB1 = (PF1);                                           \
    }

    #pragma unroll 2
    for (int t = 0; t < TT - 2; t++) {
        const float* pn = prow + (size_t)(t + 2) * G4;
        float preC0 = pn[l];
        float preC1 = (l < 8) ? pn[32 + l] : 0.f;
        STEP_BODY(preC0, preC1)
    }
    for (int t = TT - 2; t < TT; t++) {
        STEP_BODY(0.f, 0.f)
    }
#undef STEP_BODY

    if (l < HH) {
        out[(size_t)TT * BB * HH + (size_t)row * HH + l]           = hown;
        out[(size_t)TT * BB * HH + (size_t)BB * HH + row * HH + l] = creg;
    }
}

extern "C" void kernel_launch(void* const* d_in, const int* in_sizes, int n_in,
                              void* d_out, int out_size)
{
    const float* x   = (const float*)d_in[0];
    const float* Wf  = (const float*)d_in[1];
    const float* bf  = (const float*)d_in[2];
    const float* pf  = (const float*)d_in[3];
    const float* Wi  = (const float*)d_in[4];
    const float* bi  = (const float*)d_in[5];
    const float* pi_ = (const float*)d_in[6];
    const float* Wu  = (const float*)d_in[7];
    const float* bu  = (const float*)d_in[8];
    const float* pu  = (const float*)d_in[9];
    const float* Wo  = (const float*)d_in[10];
    const float* bo  = (const float*)d_in[11];
    const float* po  = (const float*)d_in[12];
    const float* lng = (const float*)d_in[13];
    const float* lnb = (const float*)d_in[14];

    k_pre<<<1024, 128>>>(x, Wf, bf, pf, Wi, bi, pi_, Wu, bu, pu, Wo, bo, po, lnb);
    k_scan<<<BB / WPB, WPB * 32>>>(Wf, pf, Wi, pi_, Wu, pu, Wo, po, lng, lnb, (float*)d_out);
}

// round 9
// speedup vs baseline: 1.5058x; 1.5058x over previous
#include <cuda_runtime.h>

// QLSTM closed form:
//   qgate(x, p)[:, w] = prod_{j<=w} cos(p[j,1]) * cos(y[:,j] + p[j,0])
// LSTM cell + residual + layernorm; sequential over T only, independent per row.

#define TT 128
#define BB 256
#define DD 64
#define HH 10
#define G4 40   // 4 gates * H
#define WROW (DD + HH)   // 74: row stride of Wg

// Layout: pre[b][t][ch]  (row-contiguous so each scan warp streams 20KB)
__device__ float g_pre[BB * TT * G4];

__device__ __forceinline__ float tanh_fast(float x) {
    float y;
    asm("tanh.approx.f32 %0, %1;" : "=f"(y) : "f"(x));
    return y;
}
__device__ __forceinline__ float sig_fast(float x) {
    return fmaf(0.5f, tanh_fast(0.5f * x), 0.5f);
}

// ---------------------------------------------------------------------------
// Kernel 1 (proven): pre[b][t][:] = fold_bias + x[t,b,:] @ Wg^T
// fold_bias = b_g[w] + p_g[w,0] + sum_j lnb_j * Whh_g[w,j]
// ---------------------------------------------------------------------------
__global__ void __launch_bounds__(128) k_pre(
    const float* __restrict__ x,
    const float* __restrict__ Wf, const float* __restrict__ bf, const float* __restrict__ pf,
    const float* __restrict__ Wi, const float* __restrict__ bi, const float* __restrict__ pi,
    const float* __restrict__ Wu, const float* __restrict__ bu, const float* __restrict__ pu,
    const float* __restrict__ Wo, const float* __restrict__ bo, const float* __restrict__ po,
    const float* __restrict__ lnb_)
{
    int tid  = threadIdx.x;
    int warp = tid >> 5, l = tid & 31;
    int wg   = blockIdx.x * 4 + warp;     // 0..4095
    int b    = wg & (BB - 1);
    int tg   = wg >> 8;                    // 0..15
    int tbase = tg * 8;

    int g0 = l / 10, w0 = l - g0 * 10;
    const float* Wg0 = (g0 == 0) ? Wf : (g0 == 1) ? Wi : (g0 == 2) ? Wu : Wo;
    const float* bg0 = (g0 == 0) ? bf : (g0 == 1) ? bi : (g0 == 2) ? bu : bo;
    const float* pg0 = (g0 == 0) ? pf : (g0 == 1) ? pi : (g0 == 2) ? pu : po;

    float wa[DD];
    #pragma unroll
    for (int d = 0; d < DD; d++) wa[d] = Wg0[w0 * WROW + d];
    float bias0 = bg0[w0] + pg0[w0 * 3 + 0];
    #pragma unroll
    for (int j = 0; j < HH; j++)
        bias0 = fmaf(lnb_[j], Wg0[w0 * WROW + DD + j], bias0);

    float wb[DD];
    float bias1 = 0.f;
    int w1 = 2 + l;
    #pragma unroll
    for (int d = 0; d < DD; d++) wb[d] = (l < 8) ? Wo[w1 * WROW + d] : 0.f;
    if (l < 8) {
        bias1 = bo[w1] + po[w1 * 3 + 0];
        #pragma unroll
        for (int j = 0; j < HH; j++)
            bias1 = fmaf(lnb_[j], Wo[w1 * WROW + DD + j], bias1);
    }

    for (int i = 0; i < 8; i++) {
        int t = tbase + i;
        const float* xr = x + ((size_t)t * BB + b) * DD;
        float x0 = xr[l];
        float x1 = xr[l + 32];

        float a0 = bias0, a0b = 0.f;
        float a1 = bias1, a1b = 0.f;
        #pragma unroll
        for (int d = 0; d < 32; d += 2) {
            float xd0 = __shfl_sync(0xffffffffu, x0, d);
            float xd1 = __shfl_sync(0xffffffffu, x0, d + 1);
            a0  = fmaf(xd0, wa[d], a0);
            a0b = fmaf(xd1, wa[d + 1], a0b);
            a1  = fmaf(xd0, wb[d], a1);
            a1b = fmaf(xd1, wb[d + 1], a1b);
        }
        #pragma unroll
        for (int d = 0; d < 32; d += 2) {
            float xd0 = __shfl_sync(0xffffffffu, x1, d);
            float xd1 = __shfl_sync(0xffffffffu, x1, d + 1);
            a0  = fmaf(xd0, wa[32 + d], a0);
            a0b = fmaf(xd1, wa[32 + d + 1], a0b);
            a1  = fmaf(xd0, wb[32 + d], a1);
            a1b = fmaf(xd1, wb[32 + d + 1], a1b);
        }
        float* pr = g_pre + ((size_t)b * TT + t) * G4;
        pr[l] = a0 + a0b;
        if (l < 8) pr[32 + l] = a1 + a1b;
    }
}

// ---------------------------------------------------------------------------
// Kernel 2: one warp per row at 1 warp/SMSP (R7 optimum), but spread over
// 128 SMs via 64-thread blocks (2 warps -> SMSP 0,1) to halve per-SM
// MIO/L1tex contention. hr-carry with sw-correction; variance via E[h2]-mu2.
// ---------------------------------------------------------------------------
__global__ void __launch_bounds__(64) k_scan(
    const float* __restrict__ Wf, const float* __restrict__ pf,
    const float* __restrict__ Wi, const float* __restrict__ pi,
    const float* __restrict__ Wu, const float* __restrict__ pu,
    const float* __restrict__ Wo, const float* __restrict__ po,
    const float* __restrict__ lng_, const float* __restrict__ lnb_,
    float* __restrict__ out)
{
    __shared__ __align__(16) float qs[2][2][48];

    int tid  = threadIdx.x;
    int warp = tid >> 5, l = tid & 31;
    int row  = blockIdx.x * 2 + warp;

    int g0 = l / 10, w0 = l - g0 * 10;
    const float* Wg0 = (g0 == 0) ? Wf : (g0 == 1) ? Wi : (g0 == 2) ? Wu : Wo;
    const float* Pg0 = (g0 == 0) ? pf : (g0 == 1) ? pi : (g0 == 2) ? pu : po;

    float cth1_0 = cosf(Pg0[w0 * 3 + 1]);
    float whh0[HH], sw0 = 0.f;
    #pragma unroll
    for (int j = 0; j < HH; j++) {
        whh0[j] = Wg0[w0 * WROW + DD + j] * lng_[j];
        sw0 += whh0[j];
    }

    int w1 = 2 + l;
    float cth1_1 = 0.f, sw1 = 0.f;
    float whh1[HH];
    #pragma unroll
    for (int j = 0; j < HH; j++) whh1[j] = 0.f;
    if (l < 8) {
        cth1_1 = cosf(po[w1 * 3 + 1]);
        #pragma unroll
        for (int j = 0; j < HH; j++) {
            whh1[j] = Wo[w1 * WROW + DD + j] * lng_[j];
            sw1 += whh1[j];
        }
    }

    float lng_l = 0.f, lnb_l = 0.f;
    if (l < HH) { lng_l = lng_[l]; lnb_l = lnb_[l]; }

    float hr[HH];
    #pragma unroll
    for (int j = 0; j < HH; j++) hr[j] = 0.f;
    float mu = 0.f, rs = 0.f, hown = 0.f, creg = 0.f;

    const float* prow = g_pre + (size_t)row * TT * G4;
    float preA0 = prow[l];
    float preA1 = (l < 8) ? prow[32 + l] : 0.f;
    float preB0 = prow[G4 + l];
    float preB1 = (l < 8) ? prow[G4 + 32 + l] : 0.f;

    float* outp = out + (size_t)row * HH;
    const size_t ostride = (size_t)BB * HH;

#define STEP_BODY(PF0, PF1)                                                     \
    {                                                                           \
        float a0 = 0.f, a1 = 0.f, a2 = 0.f, a3 = 0.f;                           \
        float c0 = 0.f, c1 = 0.f, c2 = 0.f, c3 = 0.f;                           \
        a0 = fmaf(hr[0], whh0[0], a0);  c0 = fmaf(hr[0], whh1[0], c0);          \
        a1 = fmaf(hr[1], whh0[1], a1);  c1 = fmaf(hr[1], whh1[1], c1);          \
        a2 = fmaf(hr[2], whh0[2], a2);  c2 = fmaf(hr[2], whh1[2], c2);          \
        a3 = fmaf(hr[3], whh0[3], a3);  c3 = fmaf(hr[3], whh1[3], c3);          \
        a0 = fmaf(hr[4], whh0[4], a0);  c0 = fmaf(hr[4], whh1[4], c0);          \
        a1 = fmaf(hr[5], whh0[5], a1);  c1 = fmaf(hr[5], whh1[5], c1);          \
        a2 = fmaf(hr[6], whh0[6], a2);  c2 = fmaf(hr[6], whh1[6], c2);          \
        a3 = fmaf(hr[7], whh0[7], a3);  c3 = fmaf(hr[7], whh1[7], c3);          \
        a0 = fmaf(hr[8], whh0[8], a0);  c0 = fmaf(hr[8], whh1[8], c0);          \
        a1 = fmaf(hr[9], whh0[9], a1);  c1 = fmaf(hr[9], whh1[9], c1);          \
        float dot0 = (a0 + a1) + (a2 + a3);                                     \
        float dot1 = (c0 + c1) + (c2 + c3);                                     \
        float y0 = fmaf(rs, fmaf(-mu, sw0, dot0), preA0);                       \
        float y1 = fmaf(rs, fmaf(-mu, sw1, dot1), preA1);                       \
        float q0 = cth1_0 * __cosf(y0);                                         \
        float q1 = cth1_1 * __cosf(y1);                                         \
        int par = t & 1;                                                        \
        qs[warp][par][g0 * 12 + w0] = q0;                                       \
        if (l < 8) qs[warp][par][3 * 12 + w1] = q1;                             \
        __syncwarp();                                                           \
        float q[4][10];                                                         \
        _Pragma("unroll")                                                       \
        for (int g = 0; g < 4; g++) {                                           \
            float4 va = *(const float4*)&qs[warp][par][g * 12 + 0];             \
            float4 vb = *(const float4*)&qs[warp][par][g * 12 + 4];             \
            float2 vc = *(const float2*)&qs[warp][par][g * 12 + 8];             \
            q[g][0] = va.x; q[g][1] = va.y; q[g][2] = va.z; q[g][3] = va.w;     \
            q[g][4] = vb.x; q[g][5] = vb.y; q[g][6] = vb.z; q[g][7] = vb.w;     \
            q[g][8] = vc.x; q[g][9] = vc.y;                                     \
        }                                                                       \
        float qm[4][10];                                                        \
        _Pragma("unroll")                                                       \
        for (int g = 0; g < 4; g++) {                                           \
            qm[g][0] = q[g][0];                                                 \
            _Pragma("unroll")                                                   \
            for (int j = 1; j < HH; j++)                                        \
                qm[g][j] = (l >= j) ? q[g][j] : 1.f;                            \
        }                                                                       \
        float p[4];                                                             \
        _Pragma("unroll")                                                       \
        for (int g = 0; g < 4; g++) {                                           \
            float m01 = qm[g][0] * qm[g][1];                                    \
            float m23 = qm[g][2] * qm[g][3];                                    \
            float m45 = qm[g][4] * qm[g][5];                                    \
            float m67 = qm[g][6] * qm[g][7];                                    \
            float m89 = qm[g][8] * qm[g][9];                                    \
            p[g] = ((m01 * m23) * (m45 * m67)) * m89;                           \
        }                                                                       \
        float fg = sig_fast(p[0]);                                              \
        float ig = sig_fast(p[1]);                                              \
        float gg = tanh_fast(p[2]);                                             \
        float og = sig_fast(p[3]);                                              \
        creg = fmaf(fg, creg, ig * gg);                                         \
        float hval = fmaf(og, tanh_fast(creg), hown);                           \
        _Pragma("unroll")                                                       \
        for (int j = 0; j < HH; j++) hr[j] = __shfl_sync(0xffffffffu, hval, j); \
        float sA = 0.f, sB = 0.f, qA = 0.f, qB = 0.f;                           \
        _Pragma("unroll")                                                       \
        for (int j = 0; j < HH; j += 2) {                                       \
            sA += hr[j];                                                        \
            sB += hr[j + 1];                                                    \
            qA = fmaf(hr[j],     hr[j],     qA);                                \
            qB = fmaf(hr[j + 1], hr[j + 1], qB);                                \
        }                                                                       \
        mu = (sA + sB) * 0.1f;                                                  \
        rs = rsqrtf(fmaf(-mu, mu, (qA + qB) * 0.1f) + 1e-5f);                   \
        hown = fmaf((hval - mu) * rs, lng_l, lnb_l);                            \
        if (l < HH) outp[l] = hown;                                             \
        outp += ostride;                                                        \
        preA0 = preB0; preA1 = preB1;                                           \
        preB0 = (PF0); preB1 = (PF1);                                           \
    }

    #pragma unroll 2
    for (int t = 0; t < TT - 2; t++) {
        const float* pn = prow + (size_t)(t + 2) * G4;
        float preC0 = pn[l];
        float preC1 = (l < 8) ? pn[32 + l] : 0.f;
        STEP_BODY(preC0, preC1)
    }
    for (int t = TT - 2; t < TT; t++) {
        STEP_BODY(0.f, 0.f)
    }
#undef STEP_BODY

    if (l < HH) {
        out[(size_t)TT * BB * HH + (size_t)row * HH + l]           = hown;
        out[(size_t)TT * BB * HH + (size_t)BB * HH + row * HH + l] = creg;
    }
}

extern "C" void kernel_launch(void* const* d_in, const int* in_sizes, int n_in,
                              void* d_out, int out_size)
{
    const float* x   = (const float*)d_in[0];
    const float* Wf  = (const float*)d_in[1];
    const float* bf  = (const float*)d_in[2];
    const float* pf  = (const float*)d_in[3];
    const float* Wi  = (const float*)d_in[4];
    const float* bi  = (const float*)d_in[5];
    const float* pi_ = (const float*)d_in[6];
    const float* Wu  = (const float*)d_in[7];
    const float* bu  = (const float*)d_in[8];
    const float* pu  = (const float*)d_in[9];
    const float* Wo  = (const float*)d_in[10];
    const float* bo  = (const float*)d_in[11];
    const float* po  = (const float*)d_in[12];
    const float* lng = (const float*)d_in[13];
    const float* lnb = (const float*)d_in[14];

    k_pre<<<1024, 128>>>(x, Wf, bf, pf, Wi, bi, pi_, Wu, bu, pu, Wo, bo, po, lnb);
    k_scan<<<BB / 2, 64>>>(Wf, pf, Wi, pi_, Wu, pu, Wo, po, lng, lnb, (float*)d_out);
}